// round 10
// baseline (speedup 1.0000x reference)
#include <cuda_runtime.h>
#include <cuda_bf16.h>
#include <cstddef>

#define EMB 256
#define HID 128
#define N_REL 10
#define LDA 136          // padded bf16 row stride (272B): LDSM conflict-free
#define TILE_B 34816     // 128*LDA*2 bytes

// ---------------- global scratch ----------------
__device__ float g_P[(size_t)100000 * 256];
__device__ float g_M[N_REL * 128 * 4];
__device__ float g_C[N_REL * 4];
__device__ __align__(16) __nv_bfloat16 g_BvH[128 * LDA];
__device__ __align__(16) __nv_bfloat16 g_BvL[128 * LDA];
__device__ __align__(16) __nv_bfloat16 g_BoH[128 * LDA];
__device__ __align__(16) __nv_bfloat16 g_BoL[128 * LDA];
__device__ __align__(16) __nv_bfloat16 g_BeH[4 * 128 * LDA];
__device__ __align__(16) __nv_bfloat16 g_BeL[4 * 128 * LDA];

// ---------------- helpers ----------------
__device__ __forceinline__ void split2(float x0, float x1, unsigned& hi, unsigned& lo) {
    __nv_bfloat162 h = __floats2bfloat162_rn(x0, x1);
    float r0 = x0 - __bfloat162float(h.x);
    float r1 = x1 - __bfloat162float(h.y);
    __nv_bfloat162 l = __floats2bfloat162_rn(r0, r1);
    hi = *(unsigned*)&h;
    lo = *(unsigned*)&l;
}
__device__ __forceinline__ void mma16816(float* d, const unsigned* a, unsigned b0, unsigned b1) {
    asm volatile(
        "mma.sync.aligned.m16n8k16.row.col.f32.bf16.bf16.f32 "
        "{%0,%1,%2,%3}, {%4,%5,%6,%7}, {%8,%9}, {%0,%1,%2,%3};"
        : "+f"(d[0]), "+f"(d[1]), "+f"(d[2]), "+f"(d[3])
        : "r"(a[0]), "r"(a[1]), "r"(a[2]), "r"(a[3]), "r"(b0), "r"(b1));
}
__device__ __forceinline__ void ldsm4(unsigned r[4], unsigned addr) {
    asm volatile("ldmatrix.sync.aligned.m8n8.x4.shared.b16 {%0,%1,%2,%3}, [%4];"
        : "=r"(r[0]), "=r"(r[1]), "=r"(r[2]), "=r"(r[3]) : "r"(addr));
}
__device__ __forceinline__ unsigned scvta(const void* p) {
    return (unsigned)__cvta_generic_to_shared(p);
}
__device__ __forceinline__ void cpasync16(unsigned daddr, const void* gptr) {
    asm volatile("cp.async.ca.shared.global [%0], [%1], 16;" :: "r"(daddr), "l"(gptr));
}
#define CP_COMMIT() asm volatile("cp.async.commit_group;" ::: "memory")
#define CP_WAIT0()  asm volatile("cp.async.wait_group 0;" ::: "memory")

__device__ __forceinline__ void copyB_async(const __nv_bfloat16* src, unsigned dst, int tid, int nthr) {
    const float4* s = (const float4*)src;
    for (int u = tid; u < 2176; u += nthr) cpasync16(dst + u * 16, s + u);
    CP_COMMIT();
}

// warp tile m32 x n32, bf16x3 terms
__device__ __forceinline__ void gemm_2t(
    const __nv_bfloat16* A1, const __nv_bfloat16* A2, const __nv_bfloat16* B,
    int wm, int wn, int lane, float d[2][4][4])
{
    int ar = (lane & 7) + ((lane >> 3) & 1) * 8;
    int ac = (lane >> 4) * 8;
    int br = (lane & 7) + (lane >> 4) * 8;
    int bc = ((lane >> 3) & 1) * 8;
    unsigned aA1[2], aA2[2], aB[2];
#pragma unroll
    for (int t = 0; t < 2; t++) {
        aA1[t] = scvta(A1 + (wm * 32 + t * 16 + ar) * LDA + ac);
        aA2[t] = scvta(A2 + (wm * 32 + t * 16 + ar) * LDA + ac);
    }
#pragma unroll
    for (int jp = 0; jp < 2; jp++)
        aB[jp] = scvta(B + (wn * 32 + jp * 16 + br) * LDA + bc);
#pragma unroll
    for (int ks = 0; ks < 8; ks++) {
        unsigned ko = ks * 32;
        unsigned a1[2][4], a2[2][4];
#pragma unroll
        for (int t = 0; t < 2; t++) { ldsm4(a1[t], aA1[t] + ko); ldsm4(a2[t], aA2[t] + ko); }
#pragma unroll
        for (int jp = 0; jp < 2; jp++) {
            unsigned bb[4];
            ldsm4(bb, aB[jp] + ko);
#pragma unroll
            for (int t = 0; t < 2; t++) {
                mma16816(d[t][jp * 2 + 0], a1[t], bb[0], bb[1]);
                mma16816(d[t][jp * 2 + 0], a2[t], bb[0], bb[1]);
                mma16816(d[t][jp * 2 + 1], a1[t], bb[2], bb[3]);
                mma16816(d[t][jp * 2 + 1], a2[t], bb[2], bb[3]);
            }
        }
    }
}
__device__ __forceinline__ void gemm_1t(
    const __nv_bfloat16* A1, const __nv_bfloat16* B,
    int wm, int wn, int lane, float d[2][4][4])
{
    int ar = (lane & 7) + ((lane >> 3) & 1) * 8;
    int ac = (lane >> 4) * 8;
    int br = (lane & 7) + (lane >> 4) * 8;
    int bc = ((lane >> 3) & 1) * 8;
    unsigned aA1[2], aB[2];
#pragma unroll
    for (int t = 0; t < 2; t++)
        aA1[t] = scvta(A1 + (wm * 32 + t * 16 + ar) * LDA + ac);
#pragma unroll
    for (int jp = 0; jp < 2; jp++)
        aB[jp] = scvta(B + (wn * 32 + jp * 16 + br) * LDA + bc);
#pragma unroll
    for (int ks = 0; ks < 8; ks++) {
        unsigned ko = ks * 32;
        unsigned a1[2][4];
#pragma unroll
        for (int t = 0; t < 2; t++) ldsm4(a1[t], aA1[t] + ko);
#pragma unroll
        for (int jp = 0; jp < 2; jp++) {
            unsigned bb[4];
            ldsm4(bb, aB[jp] + ko);
#pragma unroll
            for (int t = 0; t < 2; t++) {
                mma16816(d[t][jp * 2 + 0], a1[t], bb[0], bb[1]);
                mma16816(d[t][jp * 2 + 1], a1[t], bb[2], bb[3]);
            }
        }
    }
}

// ---------------------------------------------------------------------------
// merged prep (blocks 0..9) + packb (blocks 10..393), 256 threads
// ---------------------------------------------------------------------------
__global__ void prep_pack_kernel(const float* __restrict__ rel_emb,
                                 const float* __restrict__ W_q,
                                 const float* __restrict__ b_q,
                                 const float* __restrict__ W_k,
                                 const float* __restrict__ b_k,
                                 const float* __restrict__ Wv,
                                 const float* __restrict__ Wo1,
                                 const float* __restrict__ Wedge) {
    if (blockIdx.x < N_REL) {
        __shared__ float qh[128];
        int r = blockIdx.x;
        int c = threadIdx.x;
        if (c < 128) {
            float s = b_q[c];
#pragma unroll 16
            for (int t = 0; t < 64; t++) s = fmaf(rel_emb[r * 64 + t], W_q[t * 128 + c], s);
            qh[c] = s;
        }
        __syncthreads();
        if (c < 128) {
            int k = c;
            float m[4] = {0.f, 0.f, 0.f, 0.f};
#pragma unroll 8
            for (int d = 0; d < 32; d++)
#pragma unroll
                for (int h = 0; h < 4; h++)
                    m[h] = fmaf(W_k[k * 128 + h * 32 + d], qh[h * 32 + d], m[h]);
            float4 m4 = {m[0], m[1], m[2], m[3]};
            *(float4*)(g_M + r * 512 + k * 4) = m4;
            if (k < 4) {
                float cc = 0.f;
#pragma unroll 8
                for (int d = 0; d < 32; d++) cc = fmaf(b_k[k * 32 + d], qh[k * 32 + d], cc);
                g_C[r * 4 + k] = cc;
            }
        }
        return;
    }
    int idx = (blockIdx.x - N_REL) * 256 + threadIdx.x;
    if (idx < 16384) {
        int n = idx & 127, k = idx >> 7;
        float x = Wv[k * 128 + n];
        __nv_bfloat16 h = __float2bfloat16(x);
        g_BvH[n * LDA + k] = h;
        g_BvL[n * LDA + k] = __float2bfloat16(x - __bfloat162float(h));
    } else if (idx < 32768) {
        int t = idx - 16384;
        int n = t & 127, k = t >> 7;
        float x = Wo1[k * 128 + n];
        __nv_bfloat16 h = __float2bfloat16(x);
        g_BoH[n * LDA + k] = h;
        g_BoL[n * LDA + k] = __float2bfloat16(x - __bfloat162float(h));
    } else if (idx < 98304) {
        int t = idx - 32768;
        int cb = t >> 15;
        int r = t & 32767;
        int k = r >> 7;
        int n = r & 127;
        int chunk = k >> 7, kl = k & 127;
        size_t o = (size_t)((cb * 2 + chunk) * 128 + n) * LDA + kl;
        float x = Wedge[(size_t)(cb * 256 + k) * 128 + n];
        __nv_bfloat16 h = __float2bfloat16(x);
        g_BeH[o] = h;
        g_BeL[o] = __float2bfloat16(x - __bfloat162float(h));
    }
}

// ---------------------------------------------------------------------------
// nodeproj: 1024 threads, 256 nodes/block, double-buffered B w/ cp.async
// smem: AH0 0, AL0 34816, AH1 69632, AL1 104448, B0 139264, B1 174080 = 208896
// ---------------------------------------------------------------------------
__global__ __launch_bounds__(1024, 1) void nodeproj_kernel(const float* __restrict__ emb,
                                                           int n_nodes) {
    extern __shared__ __align__(16) char sm[];
    unsigned sb = scvta(sm);
    int tid = threadIdx.x;
    int lane = tid & 31, wid = tid >> 5;
    int g = lane >> 2, tk = lane & 3;
    int wid16 = wid & 15, tile_w = wid >> 4;
    int wm = wid16 >> 2, wn = wid16 & 3;
    int n0 = blockIdx.x * 256;
    int cb = blockIdx.y;
    __nv_bfloat16* AHt = (__nv_bfloat16*)(sm + tile_w * 69632);
    __nv_bfloat16* ALt = AHt + 128 * LDA;
    __nv_bfloat16* B0 = (__nv_bfloat16*)(sm + 139264);
    __nv_bfloat16* B1 = (__nv_bfloat16*)(sm + 174080);

    float d[2][4][4];
#pragma unroll
    for (int t = 0; t < 2; t++)
#pragma unroll
        for (int j = 0; j < 4; j++)
#pragma unroll
            for (int c = 0; c < 4; c++) d[t][j][c] = 0.f;

    // chunk 0: B0 <- BeH(c0)
    copyB_async(g_BeH + (size_t)(cb * 2 + 0) * 128 * LDA, sb + 139264, tid, 1024);
    // build A chunk0
    {
        int row = tid >> 2, q = tid & 3;
        int n = n0 + row; if (n >= n_nodes) n = n_nodes - 1;
        __nv_bfloat16* AH = (__nv_bfloat16*)(sm + (row >> 7) * 69632);
        __nv_bfloat16* AL = AH + 128 * LDA;
        int lr = row & 127;
        const float4* np = (const float4*)(emb + (size_t)n * EMB);
#pragma unroll
        for (int u = 0; u < 8; u++) {
            int idx = q + u * 4;
            float4 v = np[idx];
            unsigned h0, l0, h1, l1;
            split2(v.x, v.y, h0, l0);
            split2(v.z, v.w, h1, l1);
            int c = idx * 4;
            *(unsigned*)(AH + lr * LDA + c) = h0;
            *(unsigned*)(AH + lr * LDA + c + 2) = h1;
            *(unsigned*)(AL + lr * LDA + c) = l0;
            *(unsigned*)(AL + lr * LDA + c + 2) = l1;
        }
    }
    CP_WAIT0();
    __syncthreads();

    copyB_async(g_BeL + (size_t)(cb * 2 + 0) * 128 * LDA, sb + 174080, tid, 1024);
    gemm_2t(AHt, ALt, B0, wm, wn, lane, d);
    CP_WAIT0();
    __syncthreads();

    copyB_async(g_BeH + (size_t)(cb * 2 + 1) * 128 * LDA, sb + 139264, tid, 1024);
    gemm_1t(AHt, B1, wm, wn, lane, d);
    CP_WAIT0();
    __syncthreads();

    // chunk 1: rebuild A, prefetch BeL(c1)
    copyB_async(g_BeL + (size_t)(cb * 2 + 1) * 128 * LDA, sb + 174080, tid, 1024);
    {
        int row = tid >> 2, q = tid & 3;
        int n = n0 + row; if (n >= n_nodes) n = n_nodes - 1;
        __nv_bfloat16* AH = (__nv_bfloat16*)(sm + (row >> 7) * 69632);
        __nv_bfloat16* AL = AH + 128 * LDA;
        int lr = row & 127;
        const float4* np = (const float4*)(emb + (size_t)n * EMB + 128);
#pragma unroll
        for (int u = 0; u < 8; u++) {
            int idx = q + u * 4;
            float4 v = np[idx];
            unsigned h0, l0, h1, l1;
            split2(v.x, v.y, h0, l0);
            split2(v.z, v.w, h1, l1);
            int c = idx * 4;
            *(unsigned*)(AH + lr * LDA + c) = h0;
            *(unsigned*)(AH + lr * LDA + c + 2) = h1;
            *(unsigned*)(AL + lr * LDA + c) = l0;
            *(unsigned*)(AL + lr * LDA + c + 2) = l1;
        }
    }
    CP_WAIT0();
    __syncthreads();

    gemm_2t(AHt, ALt, B0, wm, wn, lane, d);
    gemm_1t(AHt, B1, wm, wn, lane, d);   // buffers ready, A untouched: no sync

    // store
#pragma unroll
    for (int t = 0; t < 2; t++) {
        int lr = wm * 32 + t * 16 + g;
#pragma unroll
        for (int j = 0; j < 4; j++) {
            int col = cb * 128 + wn * 32 + j * 8 + 2 * tk;
            int n = n0 + tile_w * 128 + lr;
            if (n < n_nodes) {
                float2 v = {d[t][j][0], d[t][j][1]};
                *(float2*)(g_P + (size_t)n * 256 + col) = v;
            }
            int n2 = n + 8;
            if (n2 < n_nodes) {
                float2 v = {d[t][j][2], d[t][j][3]};
                *(float2*)(g_P + (size_t)n2 * 256 + col) = v;
            }
        }
    }
}

// ---------------------------------------------------------------------------
// edge kernel: 1024 threads, 256 edges/block, double-buffered B w/ cp.async
// smem: AH0 0, AL0 34816, AH1 69632, AL1 104448, B0 139264, B1 174080,
//   sSc 208896(4096), sSrc 212992(1024), sTgt 214016, sRel 215040,
//   sBv 216064(512), sBo 216576, sW2 217088, sOut 217600(4096) = 221696
// ---------------------------------------------------------------------------
__global__ __launch_bounds__(1024, 1) void edge_kernel(
    const int* __restrict__ edge_index, const int* __restrict__ rel_type,
    const float* __restrict__ b_edge,
    const float* __restrict__ b_v, const float* __restrict__ b_o1,
    const float* __restrict__ W_o2, const float* __restrict__ b_o2,
    float* __restrict__ out, int E) {
    extern __shared__ __align__(16) char sm[];
    unsigned sb = scvta(sm);
    __nv_bfloat16* B0 = (__nv_bfloat16*)(sm + 139264);
    __nv_bfloat16* B1 = (__nv_bfloat16*)(sm + 174080);
    float* sSc = (float*)(sm + 208896);
    int* sSrc  = (int*)(sm + 212992);
    int* sTgt  = (int*)(sm + 214016);
    int* sRel  = (int*)(sm + 215040);
    float* sBv = (float*)(sm + 216064);
    float* sBo = (float*)(sm + 216576);
    float* sW2 = (float*)(sm + 217088);
    float* sOut = (float*)(sm + 217600);

    int tid = threadIdx.x;
    int lane = tid & 31, wid = tid >> 5;
    int g = lane >> 2, tk = lane & 3;
    int wid16 = wid & 15, tile_w = wid >> 4;
    int wm = wid16 >> 2, wn = wid16 & 3;
    int e0 = blockIdx.x * 256;
    __nv_bfloat16* AHt = (__nv_bfloat16*)(sm + tile_w * 69632);
    __nv_bfloat16* ALt = AHt + 128 * LDA;

    // stage + prefetch BvH
    copyB_async(g_BvH, sb + 139264, tid, 1024);
    if (tid < 256) {
        int e = e0 + tid;
        int eg = e < E ? e : E - 1;
        sSrc[tid] = edge_index[eg];
        sTgt[tid] = edge_index[E + eg];
        sRel[tid] = rel_type[eg];
    }
    if (tid < 128) { sBv[tid] = b_v[tid]; sBo[tid] = b_o1[tid]; sW2[tid] = W_o2[tid]; }
    __syncthreads();   // sSrc/sTgt visible for build

    // build hs, split; 4 thr/row over 256 rows
    {
        int row = tid >> 2, q = tid & 3;
        __nv_bfloat16* AH = (__nv_bfloat16*)(sm + (row >> 7) * 69632);
        __nv_bfloat16* AL = AH + 128 * LDA;
        int lr = row & 127;
        const float4* ps = (const float4*)(g_P + (size_t)sSrc[row] * 256);
        const float4* pt = (const float4*)(g_P + (size_t)sTgt[row] * 256 + 128);
        const float4* bb = (const float4*)b_edge;
#pragma unroll
        for (int u = 0; u < 8; u++) {
            int idx = q + u * 4;
            float4 a = ps[idx], b = pt[idx], c = bb[idx];
            float x0 = fmaxf(a.x + b.x + c.x, 0.f);
            float x1 = fmaxf(a.y + b.y + c.y, 0.f);
            float x2 = fmaxf(a.z + b.z + c.z, 0.f);
            float x3 = fmaxf(a.w + b.w + c.w, 0.f);
            unsigned h0, l0, h1, l1;
            split2(x0, x1, h0, l0);
            split2(x2, x3, h1, l1);
            int cc = idx * 4;
            *(unsigned*)(AH + lr * LDA + cc) = h0;
            *(unsigned*)(AH + lr * LDA + cc + 2) = h1;
            *(unsigned*)(AL + lr * LDA + cc) = l0;
            *(unsigned*)(AL + lr * LDA + cc + 2) = l1;
        }
    }
    CP_WAIT0();
    __syncthreads();   // sync1: A ready, B0=BvH ready

    // scores: 64 ty-groups x 4 edges (overlaps with other warps starting GEMM)
    {
        int tx = tid & 15, ty = tid >> 4;
#pragma unroll
        for (int i = 0; i < 4; i++) {
            int e = ty * 4 + i;
            int r = sRel[e];
            const __nv_bfloat16* AH = (const __nv_bfloat16*)(sm + (e >> 7) * 69632);
            const __nv_bfloat16* AL = AH + 128 * LDA;
            int lr = e & 127;
            const float4* gm = (const float4*)(g_M + r * 512);
            float p[4] = {0.f, 0.f, 0.f, 0.f};
#pragma unroll
            for (int j = 0; j < 4; j++) {
                int k = j * 32 + 2 * tx;
                float2 xh = __bfloat1622float2(*(const __nv_bfloat162*)(AH + lr * LDA + k));
                float2 xl = __bfloat1622float2(*(const __nv_bfloat162*)(AL + lr * LDA + k));
                float h0 = xh.x + xl.x, h1 = xh.y + xl.y;
                float4 m0 = __ldg(gm + k);
                float4 m1 = __ldg(gm + k + 1);
                p[0] += h0 * m0.x + h1 * m1.x;
                p[1] += h0 * m0.y + h1 * m1.y;
                p[2] += h0 * m0.z + h1 * m1.z;
                p[3] += h0 * m0.w + h1 * m1.w;
            }
#pragma unroll
            for (int m = 1; m < 16; m <<= 1)
#pragma unroll
                for (int j = 0; j < 4; j++) p[j] += __shfl_xor_sync(0xffffffffu, p[j], m);
            if (tx == 0) {
#pragma unroll
                for (int j = 0; j < 4; j++)
                    sSc[e * 4 + j] = (p[j] + __ldg(g_C + r * 4 + j)) * 0.17677669529663687f;
            }
        }
    }

    // GEMM1 term a: Ah*BvH + Al*BvH; prefetch BvL
    copyB_async(g_BvL, sb + 174080, tid, 1024);
    float d[2][4][4];
#pragma unroll
    for (int t = 0; t < 2; t++)
#pragma unroll
        for (int j = 0; j < 4; j++)
#pragma unroll
            for (int c = 0; c < 4; c++) d[t][j][c] = 0.f;
    gemm_2t(AHt, ALt, B0, wm, wn, lane, d);
    CP_WAIT0();
    __syncthreads();   // sync2: BvL ready, all done with B0

    // GEMM1 term b: Ah*BvL; prefetch BoH into B0
    copyB_async(g_BoH, sb + 139264, tid, 1024);
    gemm_1t(AHt, B1, wm, wn, lane, d);
    CP_WAIT0();
    __syncthreads();   // sync3: BoH ready, all done with B1 and A reads

    // epilogue1 + prefetch BoL into B1
    copyB_async(g_BoL, sb + 174080, tid, 1024);
#pragma unroll
    for (int t = 0; t < 2; t++) {
#pragma unroll
        for (int ch = 0; ch < 2; ch++) {
            int lr = wm * 32 + t * 16 + g + ch * 8;
            int e = tile_w * 128 + lr;
            float s0 = sSc[e * 4 + 0], s1 = sSc[e * 4 + 1];
            float s2 = sSc[e * 4 + 2], s3 = sSc[e * 4 + 3];
            float mx = fmaxf(fmaxf(s0, s1), fmaxf(s2, s3));
            float x0 = __expf(s0 - mx), x1 = __expf(s1 - mx);
            float x2 = __expf(s2 - mx), x3 = __expf(s3 - mx);
            float inv = 1.f / (x0 + x1 + x2 + x3);
            float aw = (wn == 0 ? x0 : wn == 1 ? x1 : wn == 2 ? x2 : x3) * inv;
#pragma unroll
            for (int j = 0; j < 4; j++) {
                int col = wn * 32 + j * 8 + 2 * tk;
                float2 xh = __bfloat1622float2(*(__nv_bfloat162*)(AHt + lr * LDA + col));
                float2 xl = __bfloat1622float2(*(__nv_bfloat162*)(ALt + lr * LDA + col));
                float v0 = d[t][j][ch * 2 + 0] + sBv[col];
                float v1 = d[t][j][ch * 2 + 1] + sBv[col + 1];
                float n0 = (xh.x + xl.x) + aw * v0;
                float n1 = (xh.y + xl.y) + aw * v1;
                unsigned hh, ll;
                split2(n0, n1, hh, ll);
                *(unsigned*)(AHt + lr * LDA + col) = hh;
                *(unsigned*)(ALt + lr * LDA + col) = ll;
            }
        }
    }
    CP_WAIT0();
    __syncthreads();   // sync4: A' complete, BoL ready

    // GEMM2: both buffers ready, A untouched between terms -> no inner sync
#pragma unroll
    for (int t = 0; t < 2; t++)
#pragma unroll
        for (int j = 0; j < 4; j++)
#pragma unroll
            for (int c = 0; c < 4; c++) d[t][j][c] = 0.f;
    gemm_2t(AHt, ALt, B0, wm, wn, lane, d);
    gemm_1t(AHt, B1, wm, wn, lane, d);

    // epilogue2
    float pacc[2][2] = {{0.f, 0.f}, {0.f, 0.f}};
#pragma unroll
    for (int t = 0; t < 2; t++)
#pragma unroll
        for (int ch = 0; ch < 2; ch++)
#pragma unroll
            for (int j = 0; j < 4; j++)
#pragma unroll
                for (int cb2 = 0; cb2 < 2; cb2++) {
                    int col = wn * 32 + j * 8 + 2 * tk + cb2;
                    float h = fmaxf(d[t][j][ch * 2 + cb2] + sBo[col], 0.f);
                    pacc[t][ch] = fmaf(h, sW2[col], pacc[t][ch]);
                }
#pragma unroll
    for (int m = 1; m <= 2; m <<= 1)
#pragma unroll
        for (int t = 0; t < 2; t++)
#pragma unroll
            for (int ch = 0; ch < 2; ch++)
                pacc[t][ch] += __shfl_xor_sync(0xffffffffu, pacc[t][ch], m);
    if (tk == 0) {
#pragma unroll
        for (int t = 0; t < 2; t++)
#pragma unroll
            for (int ch = 0; ch < 2; ch++) {
                int e = tile_w * 128 + wm * 32 + t * 16 + g + ch * 8;
                sOut[wn * 256 + e] = pacc[t][ch];
            }
    }
    __syncthreads();   // sync5
    if (tid < 256) {
        int e = e0 + tid;
        if (e < E)
            out[e] = sOut[tid] + sOut[256 + tid] + sOut[512 + tid] + sOut[768 + tid] + __ldg(b_o2);
    }
}

// ---------------------------------------------------------------------------
extern "C" void kernel_launch(void* const* d_in, const int* in_sizes, int n_in,
                              void* d_out, int out_size) {
    const float* node_emb = (const float*)d_in[0];
    const int*   edge_index = (const int*)d_in[1];
    const int*   rel_type = (const int*)d_in[2];
    const float* rel_emb = (const float*)d_in[3];
    const float* W_edge = (const float*)d_in[4];
    const float* b_edge = (const float*)d_in[5];
    const float* W_q = (const float*)d_in[6];
    const float* b_q = (const float*)d_in[7];
    const float* W_k = (const float*)d_in[8];
    const float* b_k = (const float*)d_in[9];
    const float* W_v = (const float*)d_in[10];
    const float* b_v = (const float*)d_in[11];
    const float* W_o1 = (const float*)d_in[12];
    const float* b_o1 = (const float*)d_in[13];
    const float* W_o2 = (const float*)d_in[14];
    const float* b_o2 = (const float*)d_in[15];
    float* out = (float*)d_out;

    int n_nodes = in_sizes[0] / EMB;   // 100000
    int E = in_sizes[2];               // 500000

    prep_pack_kernel<<<N_REL + 384, 256>>>(rel_emb, W_q, b_q, W_k, b_k, W_v, W_o1, W_edge);

    const int SMEM_NP = 208896;
    cudaFuncSetAttribute(nodeproj_kernel, cudaFuncAttributeMaxDynamicSharedMemorySize, SMEM_NP);
    dim3 g2((n_nodes + 255) / 256, 2);
    nodeproj_kernel<<<g2, 1024, SMEM_NP>>>(node_emb, n_nodes);

    const int SMEM_E = 221696;
    cudaFuncSetAttribute(edge_kernel, cudaFuncAttributeMaxDynamicSharedMemorySize, SMEM_E);
    edge_kernel<<<(E + 255) / 256, 1024, SMEM_E>>>(
        edge_index, rel_type, b_edge, b_v, b_o1, W_o2, b_o2, out, E);
}

// round 11
// speedup vs baseline: 1.4281x; 1.4281x over previous
#include <cuda_runtime.h>
#include <cuda_bf16.h>
#include <cstddef>

#define EMB 256
#define HID 128
#define N_REL 10
#define LDA 136   // A row stride (272B): rows step 4 banks -> LDSM conflict-free
#define LDB 72    // half-K B row stride (144B): rows step 4 banks -> conflict-free

// ---------------- global scratch ----------------
__device__ float g_P[(size_t)100000 * 256];
__device__ float g_M[N_REL * 128 * 4];
__device__ float g_C[N_REL * 4];
__device__ __align__(16) __nv_bfloat16 g_BvH[128 * LDA];
__device__ __align__(16) __nv_bfloat16 g_BvL[128 * LDA];
__device__ __align__(16) __nv_bfloat16 g_BoH[128 * LDA];
__device__ __align__(16) __nv_bfloat16 g_BoL[128 * LDA];
__device__ __align__(16) __nv_bfloat16 g_BeH[4 * 128 * LDA];
__device__ __align__(16) __nv_bfloat16 g_BeL[4 * 128 * LDA];

// ---------------- helpers ----------------
__device__ __forceinline__ void split2(float x0, float x1, unsigned& hi, unsigned& lo) {
    __nv_bfloat162 h = __floats2bfloat162_rn(x0, x1);
    float r0 = x0 - __bfloat162float(h.x);
    float r1 = x1 - __bfloat162float(h.y);
    __nv_bfloat162 l = __floats2bfloat162_rn(r0, r1);
    hi = *(unsigned*)&h;
    lo = *(unsigned*)&l;
}
__device__ __forceinline__ void mma16816(float* d, const unsigned* a, unsigned b0, unsigned b1) {
    asm volatile(
        "mma.sync.aligned.m16n8k16.row.col.f32.bf16.bf16.f32 "
        "{%0,%1,%2,%3}, {%4,%5,%6,%7}, {%8,%9}, {%0,%1,%2,%3};"
        : "+f"(d[0]), "+f"(d[1]), "+f"(d[2]), "+f"(d[3])
        : "r"(a[0]), "r"(a[1]), "r"(a[2]), "r"(a[3]), "r"(b0), "r"(b1));
}
__device__ __forceinline__ void ldsm4(unsigned r[4], unsigned addr) {
    asm volatile("ldmatrix.sync.aligned.m8n8.x4.shared.b16 {%0,%1,%2,%3}, [%4];"
        : "=r"(r[0]), "=r"(r[1]), "=r"(r[2]), "=r"(r[3]) : "r"(addr));
}
__device__ __forceinline__ unsigned scvta(const void* p) {
    return (unsigned)__cvta_generic_to_shared(p);
}
__device__ __forceinline__ void cpasync16(unsigned daddr, const void* gptr) {
    asm volatile("cp.async.ca.shared.global [%0], [%1], 16;" :: "r"(daddr), "l"(gptr));
}
#define CP_COMMIT() asm volatile("cp.async.commit_group;" ::: "memory")
#define CP_WAIT0()  asm volatile("cp.async.wait_group 0;" ::: "memory")

// copy a half-K (64-col) chunk: src points at column base within full-LDA row
__device__ __forceinline__ void copyBh(const __nv_bfloat16* src, unsigned dst, int tid) {
    const char* s = (const char*)src;
    for (int u = tid; u < 1024; u += 512) {
        int n = u >> 3, q = u & 7;
        cpasync16(dst + n * 144 + q * 16, s + n * 272 + q * 16);
    }
    CP_COMMIT();
}

// half-K GEMM steps (4 ks of k16). koff = A column base (0 or 64).
__device__ __forceinline__ void gemm_2t_h(
    const __nv_bfloat16* A1, const __nv_bfloat16* A2, int koff, const __nv_bfloat16* B,
    int wm, int wn, int lane, float d[2][4][4])
{
    int ar = (lane & 7) + ((lane >> 3) & 1) * 8;
    int ac = (lane >> 4) * 8;
    int br = (lane & 7) + (lane >> 4) * 8;
    int bc = ((lane >> 3) & 1) * 8;
    unsigned aA1[2], aA2[2], aB[2];
#pragma unroll
    for (int t = 0; t < 2; t++) {
        aA1[t] = scvta(A1 + (wm * 32 + t * 16 + ar) * LDA + koff + ac);
        aA2[t] = scvta(A2 + (wm * 32 + t * 16 + ar) * LDA + koff + ac);
    }
#pragma unroll
    for (int jp = 0; jp < 2; jp++)
        aB[jp] = scvta(B + (wn * 32 + jp * 16 + br) * LDB + bc);
#pragma unroll
    for (int ks = 0; ks < 4; ks++) {
        unsigned ko = ks * 32;
        unsigned a1[2][4], a2[2][4];
#pragma unroll
        for (int t = 0; t < 2; t++) { ldsm4(a1[t], aA1[t] + ko); ldsm4(a2[t], aA2[t] + ko); }
#pragma unroll
        for (int jp = 0; jp < 2; jp++) {
            unsigned bb[4];
            ldsm4(bb, aB[jp] + ko);
#pragma unroll
            for (int t = 0; t < 2; t++) {
                mma16816(d[t][jp * 2 + 0], a1[t], bb[0], bb[1]);
                mma16816(d[t][jp * 2 + 0], a2[t], bb[0], bb[1]);
                mma16816(d[t][jp * 2 + 1], a1[t], bb[2], bb[3]);
                mma16816(d[t][jp * 2 + 1], a2[t], bb[2], bb[3]);
            }
        }
    }
}
__device__ __forceinline__ void gemm_1t_h(
    const __nv_bfloat16* A1, int koff, const __nv_bfloat16* B,
    int wm, int wn, int lane, float d[2][4][4])
{
    int ar = (lane & 7) + ((lane >> 3) & 1) * 8;
    int ac = (lane >> 4) * 8;
    int br = (lane & 7) + (lane >> 4) * 8;
    int bc = ((lane >> 3) & 1) * 8;
    unsigned aA1[2], aB[2];
#pragma unroll
    for (int t = 0; t < 2; t++)
        aA1[t] = scvta(A1 + (wm * 32 + t * 16 + ar) * LDA + koff + ac);
#pragma unroll
    for (int jp = 0; jp < 2; jp++)
        aB[jp] = scvta(B + (wn * 32 + jp * 16 + br) * LDB + bc);
#pragma unroll
    for (int ks = 0; ks < 4; ks++) {
        unsigned ko = ks * 32;
        unsigned a1[2][4];
#pragma unroll
        for (int t = 0; t < 2; t++) ldsm4(a1[t], aA1[t] + ko);
#pragma unroll
        for (int jp = 0; jp < 2; jp++) {
            unsigned bb[4];
            ldsm4(bb, aB[jp] + ko);
#pragma unroll
            for (int t = 0; t < 2; t++) {
                mma16816(d[t][jp * 2 + 0], a1[t], bb[0], bb[1]);
                mma16816(d[t][jp * 2 + 1], a1[t], bb[2], bb[3]);
            }
        }
    }
}

// ---------------------------------------------------------------------------
// merged prep (blocks 0..9) + packb (blocks 10..393)
// ---------------------------------------------------------------------------
__global__ void prep_pack_kernel(const float* __restrict__ rel_emb,
                                 const float* __restrict__ W_q,
                                 const float* __restrict__ b_q,
                                 const float* __restrict__ W_k,
                                 const float* __restrict__ b_k,
                                 const float* __restrict__ Wv,
                                 const float* __restrict__ Wo1,
                                 const float* __restrict__ Wedge) {
    if (blockIdx.x < N_REL) {
        __shared__ float qh[128];
        int r = blockIdx.x;
        int c = threadIdx.x;
        if (c < 128) {
            float s = b_q[c];
#pragma unroll 16
            for (int t = 0; t < 64; t++) s = fmaf(rel_emb[r * 64 + t], W_q[t * 128 + c], s);
            qh[c] = s;
        }
        __syncthreads();
        if (c < 128) {
            int k = c;
            float m[4] = {0.f, 0.f, 0.f, 0.f};
#pragma unroll 8
            for (int d = 0; d < 32; d++)
#pragma unroll
                for (int h = 0; h < 4; h++)
                    m[h] = fmaf(W_k[k * 128 + h * 32 + d], qh[h * 32 + d], m[h]);
            float4 m4 = {m[0], m[1], m[2], m[3]};
            *(float4*)(g_M + r * 512 + k * 4) = m4;
            if (k < 4) {
                float cc = 0.f;
#pragma unroll 8
                for (int d = 0; d < 32; d++) cc = fmaf(b_k[k * 32 + d], qh[k * 32 + d], cc);
                g_C[r * 4 + k] = cc;
            }
        }
        return;
    }
    int idx = (blockIdx.x - N_REL) * 256 + threadIdx.x;
    if (idx < 16384) {
        int n = idx & 127, k = idx >> 7;
        float x = Wv[k * 128 + n];
        __nv_bfloat16 h = __float2bfloat16(x);
        g_BvH[n * LDA + k] = h;
        g_BvL[n * LDA + k] = __float2bfloat16(x - __bfloat162float(h));
    } else if (idx < 32768) {
        int t = idx - 16384;
        int n = t & 127, k = t >> 7;
        float x = Wo1[k * 128 + n];
        __nv_bfloat16 h = __float2bfloat16(x);
        g_BoH[n * LDA + k] = h;
        g_BoL[n * LDA + k] = __float2bfloat16(x - __bfloat162float(h));
    } else if (idx < 98304) {
        int t = idx - 32768;
        int cb = t >> 15;
        int r = t & 32767;
        int k = r >> 7;
        int n = r & 127;
        int chunk = k >> 7, kl = k & 127;
        size_t o = (size_t)((cb * 2 + chunk) * 128 + n) * LDA + kl;
        float x = Wedge[(size_t)(cb * 256 + k) * 128 + n];
        __nv_bfloat16 h = __float2bfloat16(x);
        g_BeH[o] = h;
        g_BeL[o] = __float2bfloat16(x - __bfloat162float(h));
    }
}

// ---------------------------------------------------------------------------
// nodeproj: 512 threads, 2 blocks/SM, half-K double-buffered B
// smem: AH 0, AL 34816, B0 69632(18432), B1 88064(18432) = 106496
// ---------------------------------------------------------------------------
__global__ __launch_bounds__(512, 2) void nodeproj_kernel(const float* __restrict__ emb,
                                                          int n_nodes) {
    extern __shared__ __align__(16) char sm[];
    unsigned sb = scvta(sm);
    __nv_bfloat16* AH = (__nv_bfloat16*)sm;
    __nv_bfloat16* AL = AH + 128 * LDA;
    __nv_bfloat16* B0 = (__nv_bfloat16*)(sm + 69632);
    __nv_bfloat16* B1 = (__nv_bfloat16*)(sm + 88064);
    const unsigned B0a = sb + 69632, B1a = sb + 88064;

    int tid = threadIdx.x;
    int lane = tid & 31, wid = tid >> 5;
    int g = lane >> 2, tk = lane & 3;
    int wm = wid >> 2, wn = wid & 3;
    int n0 = blockIdx.x * 128;
    int cb = blockIdx.y;
    const __nv_bfloat16* BH0 = g_BeH + (size_t)(cb * 2 + 0) * 128 * LDA;
    const __nv_bfloat16* BL0 = g_BeL + (size_t)(cb * 2 + 0) * 128 * LDA;
    const __nv_bfloat16* BH1 = g_BeH + (size_t)(cb * 2 + 1) * 128 * LDA;
    const __nv_bfloat16* BL1 = g_BeL + (size_t)(cb * 2 + 1) * 128 * LDA;

    float d[2][4][4];
#pragma unroll
    for (int t = 0; t < 2; t++)
#pragma unroll
        for (int j = 0; j < 4; j++)
#pragma unroll
            for (int c = 0; c < 4; c++) d[t][j][c] = 0.f;

    // build A(chunk0) while prefetching BH0 half0
    copyBh(BH0, B0a, tid);
    {
        int row = tid >> 2, q = tid & 3;
        int n = n0 + row; if (n >= n_nodes) n = n_nodes - 1;
        const float4* np = (const float4*)(emb + (size_t)n * EMB);
#pragma unroll
        for (int u = 0; u < 8; u++) {
            int idx = q + u * 4;
            float4 v = np[idx];
            unsigned h0, l0, h1, l1;
            split2(v.x, v.y, h0, l0);
            split2(v.z, v.w, h1, l1);
            int c = idx * 4;
            *(unsigned*)(AH + row * LDA + c) = h0;
            *(unsigned*)(AH + row * LDA + c + 2) = h1;
            *(unsigned*)(AL + row * LDA + c) = l0;
            *(unsigned*)(AL + row * LDA + c + 2) = l1;
        }
    }
    CP_WAIT0(); __syncthreads();

    copyBh(BH0 + 64, B1a, tid);
    gemm_2t_h(AH, AL, 0, B0, wm, wn, lane, d);
    CP_WAIT0(); __syncthreads();
    copyBh(BL0, B0a, tid);
    gemm_2t_h(AH, AL, 64, B1, wm, wn, lane, d);
    CP_WAIT0(); __syncthreads();
    copyBh(BL0 + 64, B1a, tid);
    gemm_1t_h(AH, 0, B0, wm, wn, lane, d);
    CP_WAIT0(); __syncthreads();
    copyBh(BH1, B0a, tid);
    gemm_1t_h(AH, 64, B1, wm, wn, lane, d);
    CP_WAIT0(); __syncthreads();

    // rebuild A(chunk1) while prefetching BH1 half1
    copyBh(BH1 + 64, B1a, tid);
    {
        int row = tid >> 2, q = tid & 3;
        int n = n0 + row; if (n >= n_nodes) n = n_nodes - 1;
        const float4* np = (const float4*)(emb + (size_t)n * EMB + 128);
#pragma unroll
        for (int u = 0; u < 8; u++) {
            int idx = q + u * 4;
            float4 v = np[idx];
            unsigned h0, l0, h1, l1;
            split2(v.x, v.y, h0, l0);
            split2(v.z, v.w, h1, l1);
            int c = idx * 4;
            *(unsigned*)(AH + row * LDA + c) = h0;
            *(unsigned*)(AH + row * LDA + c + 2) = h1;
            *(unsigned*)(AL + row * LDA + c) = l0;
            *(unsigned*)(AL + row * LDA + c + 2) = l1;
        }
    }
    CP_WAIT0(); __syncthreads();

    gemm_2t_h(AH, AL, 0, B0, wm, wn, lane, d);
    __syncthreads();                       // free B0
    copyBh(BL1, B0a, tid);
    gemm_2t_h(AH, AL, 64, B1, wm, wn, lane, d);
    CP_WAIT0(); __syncthreads();
    copyBh(BL1 + 64, B1a, tid);
    gemm_1t_h(AH, 0, B0, wm, wn, lane, d);
    CP_WAIT0(); __syncthreads();
    gemm_1t_h(AH, 64, B1, wm, wn, lane, d);

    // store
#pragma unroll
    for (int t = 0; t < 2; t++) {
        int lr = wm * 32 + t * 16 + g;
#pragma unroll
        for (int j = 0; j < 4; j++) {
            int col = cb * 128 + wn * 32 + j * 8 + 2 * tk;
            int n = n0 + lr;
            if (n < n_nodes) {
                float2 v = {d[t][j][0], d[t][j][1]};
                *(float2*)(g_P + (size_t)n * 256 + col) = v;
            }
            int n2 = n0 + lr + 8;
            if (n2 < n_nodes) {
                float2 v = {d[t][j][2], d[t][j][3]};
                *(float2*)(g_P + (size_t)n2 * 256 + col) = v;
            }
        }
    }
}

// ---------------------------------------------------------------------------
// edge kernel: 512 threads, 2 blocks/SM, half-K double-buffered B
// smem: AH 0, AL 34816, B0 69632, B1 88064, sSc 106496(2048),
//   sSrc 108544, sTgt 109056, sRel 109568, sBv 110080, sBo 110592,
//   sW2 111104, sOut 111616(2048) = 113664
// ---------------------------------------------------------------------------
__global__ __launch_bounds__(512, 2) void edge_kernel(
    const int* __restrict__ edge_index, const int* __restrict__ rel_type,
    const float* __restrict__ b_edge,
    const float* __restrict__ b_v, const float* __restrict__ b_o1,
    const float* __restrict__ W_o2, const float* __restrict__ b_o2,
    float* __restrict__ out, int E) {
    extern __shared__ __align__(16) char sm[];
    unsigned sb = scvta(sm);
    __nv_bfloat16* AH = (__nv_bfloat16*)sm;
    __nv_bfloat16* AL = AH + 128 * LDA;
    __nv_bfloat16* B0 = (__nv_bfloat16*)(sm + 69632);
    __nv_bfloat16* B1 = (__nv_bfloat16*)(sm + 88064);
    const unsigned B0a = sb + 69632, B1a = sb + 88064;
    float* sSc = (float*)(sm + 106496);
    int* sSrc  = (int*)(sm + 108544);
    int* sTgt  = (int*)(sm + 109056);
    int* sRel  = (int*)(sm + 109568);
    float* sBv = (float*)(sm + 110080);
    float* sBo = (float*)(sm + 110592);
    float* sW2 = (float*)(sm + 111104);
    float* sOut = (float*)(sm + 111616);

    int tid = threadIdx.x;
    int lane = tid & 31, wid = tid >> 5;
    int g = lane >> 2, tk = lane & 3;
    int wm = wid >> 2, wn = wid & 3;
    int e0 = blockIdx.x * 128;

    copyBh(g_BvH, B0a, tid);
    if (tid < 128) {
        int e = e0 + tid;
        int eg = e < E ? e : E - 1;
        sSrc[tid] = edge_index[eg];
        sTgt[tid] = edge_index[E + eg];
        sRel[tid] = rel_type[eg];
        sBv[tid] = b_v[tid];
        sBo[tid] = b_o1[tid];
        sW2[tid] = W_o2[tid];
    }
    __syncthreads();

    // build hs, split; 4 thr/row
    {
        int row = tid >> 2, q = tid & 3;
        const float4* ps = (const float4*)(g_P + (size_t)sSrc[row] * 256);
        const float4* pt = (const float4*)(g_P + (size_t)sTgt[row] * 256 + 128);
        const float4* bb = (const float4*)b_edge;
#pragma unroll
        for (int u = 0; u < 8; u++) {
            int idx = q + u * 4;
            float4 a = ps[idx], b = pt[idx], c = bb[idx];
            float x0 = fmaxf(a.x + b.x + c.x, 0.f);
            float x1 = fmaxf(a.y + b.y + c.y, 0.f);
            float x2 = fmaxf(a.z + b.z + c.z, 0.f);
            float x3 = fmaxf(a.w + b.w + c.w, 0.f);
            unsigned h0, l0, h1, l1;
            split2(x0, x1, h0, l0);
            split2(x2, x3, h1, l1);
            int cc = idx * 4;
            *(unsigned*)(AH + row * LDA + cc) = h0;
            *(unsigned*)(AH + row * LDA + cc + 2) = h1;
            *(unsigned*)(AL + row * LDA + cc) = l0;
            *(unsigned*)(AL + row * LDA + cc + 2) = l1;
        }
    }
    CP_WAIT0(); __syncthreads();   // A ready, B0 = BvH half0 ready

    // scores
    {
        int tx = tid & 15, ty = tid >> 4;
#pragma unroll
        for (int i = 0; i < 4; i++) {
            int e = ty * 4 + i;
            int r = sRel[e];
            const float4* gm = (const float4*)(g_M + r * 512);
            float p[4] = {0.f, 0.f, 0.f, 0.f};
#pragma unroll
            for (int j = 0; j < 4; j++) {
                int k = j * 32 + 2 * tx;
                float2 xh = __bfloat1622float2(*(const __nv_bfloat162*)(AH + e * LDA + k));
                float2 xl = __bfloat1622float2(*(const __nv_bfloat162*)(AL + e * LDA + k));
                float h0 = xh.x + xl.x, h1 = xh.y + xl.y;
                float4 m0 = __ldg(gm + k);
                float4 m1 = __ldg(gm + k + 1);
                p[0] += h0 * m0.x + h1 * m1.x;
                p[1] += h0 * m0.y + h1 * m1.y;
                p[2] += h0 * m0.z + h1 * m1.z;
                p[3] += h0 * m0.w + h1 * m1.w;
            }
#pragma unroll
            for (int m = 1; m < 16; m <<= 1)
#pragma unroll
                for (int j = 0; j < 4; j++) p[j] += __shfl_xor_sync(0xffffffffu, p[j], m);
            if (tx == 0) {
#pragma unroll
                for (int j = 0; j < 4; j++)
                    sSc[e * 4 + j] = (p[j] + __ldg(g_C + r * 4 + j)) * 0.17677669529663687f;
            }
        }
    }

    // GEMM1 pipeline (D1 = hs @ Wv^T, bf16x3)
    float d[2][4][4];
#pragma unroll
    for (int t = 0; t < 2; t++)
#pragma unroll
        for (int j = 0; j < 4; j++)
#pragma unroll
            for (int c = 0; c < 4; c++) d[t][j][c] = 0.f;
    copyBh(g_BvH + 64, B1a, tid);
    gemm_2t_h(AH, AL, 0, B0, wm, wn, lane, d);
    CP_WAIT0(); __syncthreads();
    copyBh(g_BvL, B0a, tid);
    gemm_2t_h(AH, AL, 64, B1, wm, wn, lane, d);
    CP_WAIT0(); __syncthreads();
    copyBh(g_BvL + 64, B1a, tid);
    gemm_1t_h(AH, 0, B0, wm, wn, lane, d);
    CP_WAIT0(); __syncthreads();
    copyBh(g_BoH, B0a, tid);
    gemm_1t_h(AH, 64, B1, wm, wn, lane, d);
    CP_WAIT0(); __syncthreads();

    // epilogue1 + prefetch BoH half1
    copyBh(g_BoH + 64, B1a, tid);
#pragma unroll
    for (int t = 0; t < 2; t++) {
#pragma unroll
        for (int ch = 0; ch < 2; ch++) {
            int row = wm * 32 + t * 16 + g + ch * 8;
            float s0 = sSc[row * 4 + 0], s1 = sSc[row * 4 + 1];
            float s2 = sSc[row * 4 + 2], s3 = sSc[row * 4 + 3];
            float mx = fmaxf(fmaxf(s0, s1), fmaxf(s2, s3));
            float x0 = __expf(s0 - mx), x1 = __expf(s1 - mx);
            float x2 = __expf(s2 - mx), x3 = __expf(s3 - mx);
            float inv = 1.f / (x0 + x1 + x2 + x3);
            float aw = (wn == 0 ? x0 : wn == 1 ? x1 : wn == 2 ? x2 : x3) * inv;
#pragma unroll
            for (int j = 0; j < 4; j++) {
                int col = wn * 32 + j * 8 + 2 * tk;
                float2 xh = __bfloat1622float2(*(__nv_bfloat162*)(AH + row * LDA + col));
                float2 xl = __bfloat1622float2(*(__nv_bfloat162*)(AL + row * LDA + col));
                float v0 = d[t][j][ch * 2 + 0] + sBv[col];
                float v1 = d[t][j][ch * 2 + 1] + sBv[col + 1];
                float n0 = (xh.x + xl.x) + aw * v0;
                float n1 = (xh.y + xl.y) + aw * v1;
                unsigned hh, ll;
                split2(n0, n1, hh, ll);
                *(unsigned*)(AH + row * LDA + col) = hh;
                *(unsigned*)(AL + row * LDA + col) = ll;
            }
        }
    }
    CP_WAIT0(); __syncthreads();   // A' complete, B0=BoH h0, B1=BoH h1

    // GEMM2 pipeline
#pragma unroll
    for (int t = 0; t < 2; t++)
#pragma unroll
        for (int j = 0; j < 4; j++)
#pragma unroll
            for (int c = 0; c < 4; c++) d[t][j][c] = 0.f;
    gemm_2t_h(AH, AL, 0, B0, wm, wn, lane, d);
    __syncthreads();                       // free B0
    copyBh(g_BoL, B0a, tid);
    gemm_2t_h(AH, AL, 64, B1, wm, wn, lane, d);
    CP_WAIT0(); __syncthreads();
    copyBh(g_BoL + 64, B1a, tid);
    gemm_1t_h(AH, 0, B0, wm, wn, lane, d);
    CP_WAIT0(); __syncthreads();
    gemm_1t_h(AH, 64, B1, wm, wn, lane, d);

    // epilogue2
    float pacc[2][2] = {{0.f, 0.f}, {0.f, 0.f}};
#pragma unroll
    for (int t = 0; t < 2; t++)
#pragma unroll
        for (int ch = 0; ch < 2; ch++)
#pragma unroll
            for (int j = 0; j < 4; j++)
#pragma unroll
                for (int cb2 = 0; cb2 < 2; cb2++) {
                    int col = wn * 32 + j * 8 + 2 * tk + cb2;
                    float h = fmaxf(d[t][j][ch * 2 + cb2] + sBo[col], 0.f);
                    pacc[t][ch] = fmaf(h, sW2[col], pacc[t][ch]);
                }
#pragma unroll
    for (int m = 1; m <= 2; m <<= 1)
#pragma unroll
        for (int t = 0; t < 2; t++)
#pragma unroll
            for (int ch = 0; ch < 2; ch++)
                pacc[t][ch] += __shfl_xor_sync(0xffffffffu, pacc[t][ch], m);
    if (tk == 0) {
#pragma unroll
        for (int t = 0; t < 2; t++)
#pragma unroll
            for (int ch = 0; ch < 2; ch++) {
                int row = wm * 32 + t * 16 + g + ch * 8;
                sOut[wn * 128 + row] = pacc[t][ch];
            }
    }
    __syncthreads();
    if (tid < 128) {
        int e = e0 + tid;
        if (e < E)
            out[e] = sOut[tid] + sOut[128 + tid] + sOut[256 + tid] + sOut[384 + tid] + __ldg(b_o2);
    }
}

// ---------------------------------------------------------------------------
extern "C" void kernel_launch(void* const* d_in, const int* in_sizes, int n_in,
                              void* d_out, int out_size) {
    const float* node_emb = (const float*)d_in[0];
    const int*   edge_index = (const int*)d_in[1];
    const int*   rel_type = (const int*)d_in[2];
    const float* rel_emb = (const float*)d_in[3];
    const float* W_edge = (const float*)d_in[4];
    const float* b_edge = (const float*)d_in[5];
    const float* W_q = (const float*)d_in[6];
    const float* b_q = (const float*)d_in[7];
    const float* W_k = (const float*)d_in[8];
    const float* b_k = (const float*)d_in[9];
    const float* W_v = (const float*)d_in[10];
    const float* b_v = (const float*)d_in[11];
    const float* W_o1 = (const float*)d_in[12];
    const float* b_o1 = (const float*)d_in[13];
    const float* W_o2 = (const float*)d_in[14];
    const float* b_o2 = (const float*)d_in[15];
    float* out = (float*)d_out;

    int n_nodes = in_sizes[0] / EMB;   // 100000
    int E = in_sizes[2];               // 500000

    prep_pack_kernel<<<N_REL + 384, 256>>>(rel_emb, W_q, b_q, W_k, b_k, W_v, W_o1, W_edge);

    const int SMEM_NP = 106496;
    cudaFuncSetAttribute(nodeproj_kernel, cudaFuncAttributeMaxDynamicSharedMemorySize, SMEM_NP);
    dim3 g2((n_nodes + 127) / 128, 2);
    nodeproj_kernel<<<g2, 512, SMEM_NP>>>(node_emb, n_nodes);

    const int SMEM_E = 113664;
    cudaFuncSetAttribute(edge_kernel, cudaFuncAttributeMaxDynamicSharedMemorySize, SMEM_E);
    edge_kernel<<<(E + 127) / 128, 512, SMEM_E>>>(
        edge_index, rel_type, b_edge, b_v, b_o1, W_o2, b_o2, out, E);
}

// round 12
// speedup vs baseline: 1.7391x; 1.2178x over previous
#include <cuda_runtime.h>
#include <cuda_bf16.h>
#include <cuda_fp16.h>
#include <cstddef>

#define EMB 256
#define HID 128
#define N_REL 10
#define LDA 136   // row stride (272B): rows step 4 banks -> LDSM conflict-free
#define LDB 72    // nodeproj half-K B row stride

// ---------------- global scratch ----------------
__device__ float g_P[(size_t)100000 * 256];
__device__ float g_M[N_REL * 128 * 4];
__device__ float g_C[N_REL * 4];
// fp16 single-precision weight images for edge kernel
__device__ __align__(16) __half g_BvF[128 * LDA];
__device__ __align__(16) __half g_BoF[128 * LDA];
// bf16 hi/lo for nodeproj (unchanged, proven)
__device__ __align__(16) __nv_bfloat16 g_BeH[4 * 128 * LDA];
__device__ __align__(16) __nv_bfloat16 g_BeL[4 * 128 * LDA];

// ---------------- helpers ----------------
__device__ __forceinline__ void split2b(float x0, float x1, unsigned& hi, unsigned& lo) {
    __nv_bfloat162 h = __floats2bfloat162_rn(x0, x1);
    float r0 = x0 - __bfloat162float(h.x);
    float r1 = x1 - __bfloat162float(h.y);
    __nv_bfloat162 l = __floats2bfloat162_rn(r0, r1);
    hi = *(unsigned*)&h;
    lo = *(unsigned*)&l;
}
__device__ __forceinline__ void split2h(float x0, float x1, unsigned& hi, unsigned& lo) {
    __half2 h = __floats2half2_rn(x0, x1);
    float r0 = x0 - __half2float(__low2half(h));
    float r1 = x1 - __half2float(__high2half(h));
    __half2 l = __floats2half2_rn(r0, r1);
    hi = *(unsigned*)&h;
    lo = *(unsigned*)&l;
}
__device__ __forceinline__ void mma_bf(float* d, const unsigned* a, unsigned b0, unsigned b1) {
    asm volatile(
        "mma.sync.aligned.m16n8k16.row.col.f32.bf16.bf16.f32 "
        "{%0,%1,%2,%3}, {%4,%5,%6,%7}, {%8,%9}, {%0,%1,%2,%3};"
        : "+f"(d[0]), "+f"(d[1]), "+f"(d[2]), "+f"(d[3])
        : "r"(a[0]), "r"(a[1]), "r"(a[2]), "r"(a[3]), "r"(b0), "r"(b1));
}
__device__ __forceinline__ void mma_fp(float* d, const unsigned* a, unsigned b0, unsigned b1) {
    asm volatile(
        "mma.sync.aligned.m16n8k16.row.col.f32.f16.f16.f32 "
        "{%0,%1,%2,%3}, {%4,%5,%6,%7}, {%8,%9}, {%0,%1,%2,%3};"
        : "+f"(d[0]), "+f"(d[1]), "+f"(d[2]), "+f"(d[3])
        : "r"(a[0]), "r"(a[1]), "r"(a[2]), "r"(a[3]), "r"(b0), "r"(b1));
}
__device__ __forceinline__ void ldsm4(unsigned r[4], unsigned addr) {
    asm volatile("ldmatrix.sync.aligned.m8n8.x4.shared.b16 {%0,%1,%2,%3}, [%4];"
        : "=r"(r[0]), "=r"(r[1]), "=r"(r[2]), "=r"(r[3]) : "r"(addr));
}
__device__ __forceinline__ unsigned scvta(const void* p) {
    return (unsigned)__cvta_generic_to_shared(p);
}
__device__ __forceinline__ void cpasync16(unsigned daddr, const void* gptr) {
    asm volatile("cp.async.ca.shared.global [%0], [%1], 16;" :: "r"(daddr), "l"(gptr));
}
#define CP_COMMIT() asm volatile("cp.async.commit_group;" ::: "memory")
#define CP_WAIT0()  asm volatile("cp.async.wait_group 0;" ::: "memory")

// full 34816B tile copy (2176 x 16B)
__device__ __forceinline__ void copyT(const void* src, unsigned dst, int tid) {
    const float4* s = (const float4*)src;
    for (int u = tid; u < 2176; u += 512) cpasync16(dst + u * 16, s + u);
    CP_COMMIT();
}
// nodeproj half-K chunk copy (src column base within full-LDA rows)
__device__ __forceinline__ void copyBh(const __nv_bfloat16* src, unsigned dst, int tid) {
    const char* s = (const char*)src;
    for (int u = tid; u < 1024; u += 512) {
        int n = u >> 3, q = u & 7;
        cpasync16(dst + n * 144 + q * 16, s + n * 272 + q * 16);
    }
    CP_COMMIT();
}

// ---------------- edge GEMM: D += (A1 + A2) @ B^T, fp16, single pass full-K ----
__device__ __forceinline__ void gemm_e(
    const __half* A1, const __half* A2, const __half* B,
    int wm, int wn, int lane, float d[2][4][4])
{
    int ar = (lane & 7) + ((lane >> 3) & 1) * 8;
    int ac = (lane >> 4) * 8;
    int br = (lane & 7) + (lane >> 4) * 8;
    int bc = ((lane >> 3) & 1) * 8;
    unsigned aA1[2], aA2[2], aB[2];
#pragma unroll
    for (int t = 0; t < 2; t++) {
        aA1[t] = scvta(A1 + (wm * 32 + t * 16 + ar) * LDA + ac);
        aA2[t] = scvta(A2 + (wm * 32 + t * 16 + ar) * LDA + ac);
    }
#pragma unroll
    for (int jp = 0; jp < 2; jp++)
        aB[jp] = scvta(B + (wn * 32 + jp * 16 + br) * LDA + bc);
#pragma unroll
    for (int ks = 0; ks < 8; ks++) {
        unsigned ko = ks * 32;
        unsigned a1[2][4], a2[2][4];
#pragma unroll
        for (int t = 0; t < 2; t++) { ldsm4(a1[t], aA1[t] + ko); ldsm4(a2[t], aA2[t] + ko); }
#pragma unroll
        for (int jp = 0; jp < 2; jp++) {
            unsigned bb[4];
            ldsm4(bb, aB[jp] + ko);
#pragma unroll
            for (int t = 0; t < 2; t++) {
                mma_fp(d[t][jp * 2 + 0], a1[t], bb[0], bb[1]);
                mma_fp(d[t][jp * 2 + 0], a2[t], bb[0], bb[1]);
                mma_fp(d[t][jp * 2 + 1], a1[t], bb[2], bb[3]);
                mma_fp(d[t][jp * 2 + 1], a2[t], bb[2], bb[3]);
            }
        }
    }
}

// ---------------- nodeproj half-K GEMMs (bf16, unchanged) ----------------
__device__ __forceinline__ void gemm_2t_h(
    const __nv_bfloat16* A1, const __nv_bfloat16* A2, int koff, const __nv_bfloat16* B,
    int wm, int wn, int lane, float d[2][4][4])
{
    int ar = (lane & 7) + ((lane >> 3) & 1) * 8;
    int ac = (lane >> 4) * 8;
    int br = (lane & 7) + (lane >> 4) * 8;
    int bc = ((lane >> 3) & 1) * 8;
    unsigned aA1[2], aA2[2], aB[2];
#pragma unroll
    for (int t = 0; t < 2; t++) {
        aA1[t] = scvta(A1 + (wm * 32 + t * 16 + ar) * LDA + koff + ac);
        aA2[t] = scvta(A2 + (wm * 32 + t * 16 + ar) * LDA + koff + ac);
    }
#pragma unroll
    for (int jp = 0; jp < 2; jp++)
        aB[jp] = scvta(B + (wn * 32 + jp * 16 + br) * LDB + bc);
#pragma unroll
    for (int ks = 0; ks < 4; ks++) {
        unsigned ko = ks * 32;
        unsigned a1[2][4], a2[2][4];
#pragma unroll
        for (int t = 0; t < 2; t++) { ldsm4(a1[t], aA1[t] + ko); ldsm4(a2[t], aA2[t] + ko); }
#pragma unroll
        for (int jp = 0; jp < 2; jp++) {
            unsigned bb[4];
            ldsm4(bb, aB[jp] + ko);
#pragma unroll
            for (int t = 0; t < 2; t++) {
                mma_bf(d[t][jp * 2 + 0], a1[t], bb[0], bb[1]);
                mma_bf(d[t][jp * 2 + 0], a2[t], bb[0], bb[1]);
                mma_bf(d[t][jp * 2 + 1], a1[t], bb[2], bb[3]);
                mma_bf(d[t][jp * 2 + 1], a2[t], bb[2], bb[3]);
            }
        }
    }
}
__device__ __forceinline__ void gemm_1t_h(
    const __nv_bfloat16* A1, int koff, const __nv_bfloat16* B,
    int wm, int wn, int lane, float d[2][4][4])
{
    int ar = (lane & 7) + ((lane >> 3) & 1) * 8;
    int ac = (lane >> 4) * 8;
    int br = (lane & 7) + (lane >> 4) * 8;
    int bc = ((lane >> 3) & 1) * 8;
    unsigned aA1[2], aB[2];
#pragma unroll
    for (int t = 0; t < 2; t++)
        aA1[t] = scvta(A1 + (wm * 32 + t * 16 + ar) * LDA + koff + ac);
#pragma unroll
    for (int jp = 0; jp < 2; jp++)
        aB[jp] = scvta(B + (wn * 32 + jp * 16 + br) * LDB + bc);
#pragma unroll
    for (int ks = 0; ks < 4; ks++) {
        unsigned ko = ks * 32;
        unsigned a1[2][4];
#pragma unroll
        for (int t = 0; t < 2; t++) ldsm4(a1[t], aA1[t] + ko);
#pragma unroll
        for (int jp = 0; jp < 2; jp++) {
            unsigned bb[4];
            ldsm4(bb, aB[jp] + ko);
#pragma unroll
            for (int t = 0; t < 2; t++) {
                mma_bf(d[t][jp * 2 + 0], a1[t], bb[0], bb[1]);
                mma_bf(d[t][jp * 2 + 1], a1[t], bb[2], bb[3]);
            }
        }
    }
}

// ---------------------------------------------------------------------------
// merged prep (blocks 0..9) + packb (blocks 10..393)
// ---------------------------------------------------------------------------
__global__ void prep_pack_kernel(const float* __restrict__ rel_emb,
                                 const float* __restrict__ W_q,
                                 const float* __restrict__ b_q,
                                 const float* __restrict__ W_k,
                                 const float* __restrict__ b_k,
                                 const float* __restrict__ Wv,
                                 const float* __restrict__ Wo1,
                                 const float* __restrict__ Wedge) {
    if (blockIdx.x < N_REL) {
        __shared__ float qh[128];
        int r = blockIdx.x;
        int c = threadIdx.x;
        if (c < 128) {
            float s = b_q[c];
#pragma unroll 16
            for (int t = 0; t < 64; t++) s = fmaf(rel_emb[r * 64 + t], W_q[t * 128 + c], s);
            qh[c] = s;
        }
        __syncthreads();
        if (c < 128) {
            int k = c;
            float m[4] = {0.f, 0.f, 0.f, 0.f};
#pragma unroll 8
            for (int d = 0; d < 32; d++)
#pragma unroll
                for (int h = 0; h < 4; h++)
                    m[h] = fmaf(W_k[k * 128 + h * 32 + d], qh[h * 32 + d], m[h]);
            float4 m4 = {m[0], m[1], m[2], m[3]};
            *(float4*)(g_M + r * 512 + k * 4) = m4;
            if (k < 4) {
                float cc = 0.f;
#pragma unroll 8
                for (int d = 0; d < 32; d++) cc = fmaf(b_k[k * 32 + d], qh[k * 32 + d], cc);
                g_C[r * 4 + k] = cc;
            }
        }
        return;
    }
    int idx = (blockIdx.x - N_REL) * 256 + threadIdx.x;
    if (idx < 16384) {
        int n = idx & 127, k = idx >> 7;
        g_BvF[n * LDA + k] = __float2half(Wv[k * 128 + n]);
    } else if (idx < 32768) {
        int t = idx - 16384;
        int n = t & 127, k = t >> 7;
        g_BoF[n * LDA + k] = __float2half(Wo1[k * 128 + n]);
    } else if (idx < 98304) {
        int t = idx - 32768;
        int cb = t >> 15;
        int r = t & 32767;
        int k = r >> 7;
        int n = r & 127;
        int chunk = k >> 7, kl = k & 127;
        size_t o = (size_t)((cb * 2 + chunk) * 128 + n) * LDA + kl;
        float x = Wedge[(size_t)(cb * 256 + k) * 128 + n];
        __nv_bfloat16 h = __float2bfloat16(x);
        g_BeH[o] = h;
        g_BeL[o] = __float2bfloat16(x - __bfloat162float(h));
    }
}

// ---------------------------------------------------------------------------
// nodeproj: 512 threads, 2 blocks/SM, half-K double-buffered B (unchanged)
// smem: AH 0, AL 34816, B0 69632, B1 88064 = 106496
// ---------------------------------------------------------------------------
__global__ __launch_bounds__(512, 2) void nodeproj_kernel(const float* __restrict__ emb,
                                                          int n_nodes) {
    extern __shared__ __align__(16) char sm[];
    unsigned sb = scvta(sm);
    __nv_bfloat16* AH = (__nv_bfloat16*)sm;
    __nv_bfloat16* AL = AH + 128 * LDA;
    __nv_bfloat16* B0 = (__nv_bfloat16*)(sm + 69632);
    __nv_bfloat16* B1 = (__nv_bfloat16*)(sm + 88064);
    const unsigned B0a = sb + 69632, B1a = sb + 88064;

    int tid = threadIdx.x;
    int lane = tid & 31, wid = tid >> 5;
    int g = lane >> 2, tk = lane & 3;
    int wm = wid >> 2, wn = wid & 3;
    int n0 = blockIdx.x * 128;
    int cb = blockIdx.y;
    const __nv_bfloat16* BH0 = g_BeH + (size_t)(cb * 2 + 0) * 128 * LDA;
    const __nv_bfloat16* BL0 = g_BeL + (size_t)(cb * 2 + 0) * 128 * LDA;
    const __nv_bfloat16* BH1 = g_BeH + (size_t)(cb * 2 + 1) * 128 * LDA;
    const __nv_bfloat16* BL1 = g_BeL + (size_t)(cb * 2 + 1) * 128 * LDA;

    float d[2][4][4];
#pragma unroll
    for (int t = 0; t < 2; t++)
#pragma unroll
        for (int j = 0; j < 4; j++)
#pragma unroll
            for (int c = 0; c < 4; c++) d[t][j][c] = 0.f;

    copyBh(BH0, B0a, tid);
    {
        int row = tid >> 2, q = tid & 3;
        int n = n0 + row; if (n >= n_nodes) n = n_nodes - 1;
        const float4* np = (const float4*)(emb + (size_t)n * EMB);
#pragma unroll
        for (int u = 0; u < 8; u++) {
            int idx = q + u * 4;
            float4 v = np[idx];
            unsigned h0, l0, h1, l1;
            split2b(v.x, v.y, h0, l0);
            split2b(v.z, v.w, h1, l1);
            int c = idx * 4;
            *(unsigned*)(AH + row * LDA + c) = h0;
            *(unsigned*)(AH + row * LDA + c + 2) = h1;
            *(unsigned*)(AL + row * LDA + c) = l0;
            *(unsigned*)(AL + row * LDA + c + 2) = l1;
        }
    }
    CP_WAIT0(); __syncthreads();

    copyBh(BH0 + 64, B1a, tid);
    gemm_2t_h(AH, AL, 0, B0, wm, wn, lane, d);
    CP_WAIT0(); __syncthreads();
    copyBh(BL0, B0a, tid);
    gemm_2t_h(AH, AL, 64, B1, wm, wn, lane, d);
    CP_WAIT0(); __syncthreads();
    copyBh(BL0 + 64, B1a, tid);
    gemm_1t_h(AH, 0, B0, wm, wn, lane, d);
    CP_WAIT0(); __syncthreads();
    copyBh(BH1, B0a, tid);
    gemm_1t_h(AH, 64, B1, wm, wn, lane, d);
    CP_WAIT0(); __syncthreads();

    copyBh(BH1 + 64, B1a, tid);
    {
        int row = tid >> 2, q = tid & 3;
        int n = n0 + row; if (n >= n_nodes) n = n_nodes - 1;
        const float4* np = (const float4*)(emb + (size_t)n * EMB + 128);
#pragma unroll
        for (int u = 0; u < 8; u++) {
            int idx = q + u * 4;
            float4 v = np[idx];
            unsigned h0, l0, h1, l1;
            split2b(v.x, v.y, h0, l0);
            split2b(v.z, v.w, h1, l1);
            int c = idx * 4;
            *(unsigned*)(AH + row * LDA + c) = h0;
            *(unsigned*)(AH + row * LDA + c + 2) = h1;
            *(unsigned*)(AL + row * LDA + c) = l0;
            *(unsigned*)(AL + row * LDA + c + 2) = l1;
        }
    }
    CP_WAIT0(); __syncthreads();

    gemm_2t_h(AH, AL, 0, B0, wm, wn, lane, d);
    __syncthreads();
    copyBh(BL1, B0a, tid);
    gemm_2t_h(AH, AL, 64, B1, wm, wn, lane, d);
    CP_WAIT0(); __syncthreads();
    copyBh(BL1 + 64, B1a, tid);
    gemm_1t_h(AH, 0, B0, wm, wn, lane, d);
    CP_WAIT0(); __syncthreads();
    gemm_1t_h(AH, 64, B1, wm, wn, lane, d);

#pragma unroll
    for (int t = 0; t < 2; t++) {
        int lr = wm * 32 + t * 16 + g;
#pragma unroll
        for (int j = 0; j < 4; j++) {
            int col = cb * 128 + wn * 32 + j * 8 + 2 * tk;
            int n = n0 + lr;
            if (n < n_nodes) {
                float2 v = {d[t][j][0], d[t][j][1]};
                *(float2*)(g_P + (size_t)n * 256 + col) = v;
            }
            int n2 = n0 + lr + 8;
            if (n2 < n_nodes) {
                float2 v = {d[t][j][2], d[t][j][3]};
                *(float2*)(g_P + (size_t)n2 * 256 + col) = v;
            }
        }
    }
}

// ---------------------------------------------------------------------------
// edge kernel: fp16 A-split / B-single 2-term, 512 threads, 2 blocks/SM
// smem: AH 0, AL 34816, BF 69632, sSc 104448(2048), sSrc 106496, sTgt 107008,
//   sRel 107520, sBv 108032, sBo 108544, sW2 109056, sOut 109568(2048) = 111616
// ---------------------------------------------------------------------------
__global__ __launch_bounds__(512, 2) void edge_kernel(
    const int* __restrict__ edge_index, const int* __restrict__ rel_type,
    const float* __restrict__ b_edge,
    const float* __restrict__ b_v, const float* __restrict__ b_o1,
    const float* __restrict__ W_o2, const float* __restrict__ b_o2,
    float* __restrict__ out, int E) {
    extern __shared__ __align__(16) char sm[];
    unsigned sb = scvta(sm);
    __half* AH = (__half*)sm;
    __half* AL = AH + 128 * LDA;
    __half* BF = (__half*)(sm + 69632);
    const unsigned BFa = sb + 69632;
    float* sSc = (float*)(sm + 104448);
    int* sSrc  = (int*)(sm + 106496);
    int* sTgt  = (int*)(sm + 107008);
    int* sRel  = (int*)(sm + 107520);
    float* sBv = (float*)(sm + 108032);
    float* sBo = (float*)(sm + 108544);
    float* sW2 = (float*)(sm + 109056);
    float* sOut = (float*)(sm + 109568);

    int tid = threadIdx.x;
    int lane = tid & 31, wid = tid >> 5;
    int g = lane >> 2, tk = lane & 3;
    int wm = wid >> 2, wn = wid & 3;
    int e0 = blockIdx.x * 128;

    copyT(g_BvF, BFa, tid);
    if (tid < 128) {
        int e = e0 + tid;
        int eg = e < E ? e : E - 1;
        sSrc[tid] = edge_index[eg];
        sTgt[tid] = edge_index[E + eg];
        sRel[tid] = rel_type[eg];
        sBv[tid] = b_v[tid];
        sBo[tid] = b_o1[tid];
        sW2[tid] = W_o2[tid];
    }
    __syncthreads();   // sync0: indices visible

    // ---- build hs (relu, fp16 hi/lo split) + FUSED scores ----
    {
        int row = tid >> 2, q = tid & 3;
        int r = sRel[row];
        const float4* ps = (const float4*)(g_P + (size_t)sSrc[row] * 256);
        const float4* pt = (const float4*)(g_P + (size_t)sTgt[row] * 256 + 128);
        const float4* bbv = (const float4*)b_edge;
        const float4* gm = (const float4*)(g_M + r * 512);
        float p0 = 0.f, p1 = 0.f, p2 = 0.f, p3 = 0.f;
#pragma unroll
        for (int u = 0; u < 8; u++) {
            int idx = q + u * 4;
            float4 a = ps[idx], b = pt[idx], c = bbv[idx];
            float x0 = fmaxf(a.x + b.x + c.x, 0.f);
            float x1 = fmaxf(a.y + b.y + c.y, 0.f);
            float x2 = fmaxf(a.z + b.z + c.z, 0.f);
            float x3 = fmaxf(a.w + b.w + c.w, 0.f);
            unsigned h0, l0, h1, l1;
            split2h(x0, x1, h0, l0);
            split2h(x2, x3, h1, l1);
            int cc = idx * 4;
            *(unsigned*)(AH + row * LDA + cc) = h0;
            *(unsigned*)(AH + row * LDA + cc + 2) = h1;
            *(unsigned*)(AL + row * LDA + cc) = l0;
            *(unsigned*)(AL + row * LDA + cc + 2) = l1;
            float4 m0 = __ldg(gm + cc), m1 = __ldg(gm + cc + 1);
            float4 m2 = __ldg(gm + cc + 2), m3 = __ldg(gm + cc + 3);
            p0 += x0 * m0.x + x1 * m1.x + x2 * m2.x + x3 * m3.x;
            p1 += x0 * m0.y + x1 * m1.y + x2 * m2.y + x3 * m3.y;
            p2 += x0 * m0.z + x1 * m1.z + x2 * m2.z + x3 * m3.z;
            p3 += x0 * m0.w + x1 * m1.w + x2 * m2.w + x3 * m3.w;
        }
#pragma unroll
        for (int m = 1; m <= 2; m <<= 1) {
            p0 += __shfl_xor_sync(0xffffffffu, p0, m);
            p1 += __shfl_xor_sync(0xffffffffu, p1, m);
            p2 += __shfl_xor_sync(0xffffffffu, p2, m);
            p3 += __shfl_xor_sync(0xffffffffu, p3, m);
        }
        if (q == 0) {
            const float sc = 0.17677669529663687f;  // 1/sqrt(32)
            sSc[row * 4 + 0] = (p0 + __ldg(g_C + r * 4 + 0)) * sc;
            sSc[row * 4 + 1] = (p1 + __ldg(g_C + r * 4 + 1)) * sc;
            sSc[row * 4 + 2] = (p2 + __ldg(g_C + r * 4 + 2)) * sc;
            sSc[row * 4 + 3] = (p3 + __ldg(g_C + r * 4 + 3)) * sc;
        }
    }
    CP_WAIT0(); __syncthreads();   // sync1: A, scores, BvF ready

    // ---- GEMM1: V = hs @ Wv^T ----
    float d[2][4][4];
#pragma unroll
    for (int t = 0; t < 2; t++)
#pragma unroll
        for (int j = 0; j < 4; j++)
#pragma unroll
            for (int c = 0; c < 4; c++) d[t][j][c] = 0.f;
    gemm_e(AH, AL, BF, wm, wn, lane, d);
    __syncthreads();   // sync2: done reading BF

    // ---- epilogue1 (softmax + residual RMW on fp16 pair) + prefetch BoF ----
    copyT(g_BoF, BFa, tid);
#pragma unroll
    for (int t = 0; t < 2; t++) {
#pragma unroll
        for (int ch = 0; ch < 2; ch++) {
            int row = wm * 32 + t * 16 + g + ch * 8;
            float s0 = sSc[row * 4 + 0], s1 = sSc[row * 4 + 1];
            float s2 = sSc[row * 4 + 2], s3 = sSc[row * 4 + 3];
            float mx = fmaxf(fmaxf(s0, s1), fmaxf(s2, s3));
            float x0 = __expf(s0 - mx), x1 = __expf(s1 - mx);
            float x2 = __expf(s2 - mx), x3 = __expf(s3 - mx);
            float inv = 1.f / (x0 + x1 + x2 + x3);
            float aw = (wn == 0 ? x0 : wn == 1 ? x1 : wn == 2 ? x2 : x3) * inv;
#pragma unroll
            for (int j = 0; j < 4; j++) {
                int col = wn * 32 + j * 8 + 2 * tk;
                float2 fh = __half22float2(*(__half2*)(AH + row * LDA + col));
                float2 fl = __half22float2(*(__half2*)(AL + row * LDA + col));
                float v0 = d[t][j][ch * 2 + 0] + sBv[col];
                float v1 = d[t][j][ch * 2 + 1] + sBv[col + 1];
                float n0 = (fh.x + fl.x) + aw * v0;
                float n1 = (fh.y + fl.y) + aw * v1;
                unsigned hh, ll;
                split2h(n0, n1, hh, ll);
                *(unsigned*)(AH + row * LDA + col) = hh;
                *(unsigned*)(AL + row * LDA + col) = ll;
            }
        }
    }
    CP_WAIT0(); __syncthreads();   // sync3: A' + BoF ready

    // ---- GEMM2 ----
#pragma unroll
    for (int t = 0; t < 2; t++)
#pragma unroll
        for (int j = 0; j < 4; j++)
#pragma unroll
            for (int c = 0; c < 4; c++) d[t][j][c] = 0.f;
    gemm_e(AH, AL, BF, wm, wn, lane, d);

    // ---- epilogue2: relu(D2 + b_o1) . W_o2 ----
    float pacc[2][2] = {{0.f, 0.f}, {0.f, 0.f}};
#pragma unroll
    for (int t = 0; t < 2; t++)
#pragma unroll
        for (int ch = 0; ch < 2; ch++)
#pragma unroll
            for (int j = 0; j < 4; j++)
#pragma unroll
                for (int cb2 = 0; cb2 < 2; cb2++) {
                    int col = wn * 32 + j * 8 + 2 * tk + cb2;
                    float h = fmaxf(d[t][j][ch * 2 + cb2] + sBo[col], 0.f);
                    pacc[t][ch] = fmaf(h, sW2[col], pacc[t][ch]);
                }
#pragma unroll
    for (int m = 1; m <= 2; m <<= 1)
#pragma unroll
        for (int t = 0; t < 2; t++)
#pragma unroll
            for (int ch = 0; ch < 2; ch++)
                pacc[t][ch] += __shfl_xor_sync(0xffffffffu, pacc[t][ch], m);
    if (tk == 0) {
#pragma unroll
        for (int t = 0; t < 2; t++)
#pragma unroll
            for (int ch = 0; ch < 2; ch++) {
                int row = wm * 32 + t * 16 + g + ch * 8;
                sOut[wn * 128 + row] = pacc[t][ch];
            }
    }
    __syncthreads();   // sync4
    if (tid < 128) {
        int e = e0 + tid;
        if (e < E)
            out[e] = sOut[tid] + sOut[128 + tid] + sOut[256 + tid] + sOut[384 + tid] + __ldg(b_o2);
    }
}

// ---------------------------------------------------------------------------
extern "C" void kernel_launch(void* const* d_in, const int* in_sizes, int n_in,
                              void* d_out, int out_size) {
    const float* node_emb = (const float*)d_in[0];
    const int*   edge_index = (const int*)d_in[1];
    const int*   rel_type = (const int*)d_in[2];
    const float* rel_emb = (const float*)d_in[3];
    const float* W_edge = (const float*)d_in[4];
    const float* b_edge = (const float*)d_in[5];
    const float* W_q = (const float*)d_in[6];
    const float* b_q = (const float*)d_in[7];
    const float* W_k = (const float*)d_in[8];
    const float* b_k = (const float*)d_in[9];
    const float* W_v = (const float*)d_in[10];
    const float* b_v = (const float*)d_in[11];
    const float* W_o1 = (const float*)d_in[12];
    const float* b_o1 = (const float*)d_in[13];
    const float* W_o2 = (const float*)d_in[14];
    const float* b_o2 = (const float*)d_in[15];
    float* out = (float*)d_out;

    int n_nodes = in_sizes[0] / EMB;   // 100000
    int E = in_sizes[2];               // 500000

    prep_pack_kernel<<<N_REL + 384, 256>>>(rel_emb, W_q, b_q, W_k, b_k, W_v, W_o1, W_edge);

    const int SMEM_NP = 106496;
    cudaFuncSetAttribute(nodeproj_kernel, cudaFuncAttributeMaxDynamicSharedMemorySize, SMEM_NP);
    dim3 g2((n_nodes + 127) / 128, 2);
    nodeproj_kernel<<<g2, 512, SMEM_NP>>>(node_emb, n_nodes);

    const int SMEM_E = 111616;
    cudaFuncSetAttribute(edge_kernel, cudaFuncAttributeMaxDynamicSharedMemorySize, SMEM_E);
    edge_kernel<<<(E + 127) / 128, 512, SMEM_E>>>(
        edge_index, rel_type, b_edge, b_v, b_o1, W_o2, b_o2, out, E);
}